// round 16
// baseline (speedup 1.0000x reference)
#include <cuda_runtime.h>
#include <cuda_bf16.h>
#include <mma.h>
#include <math.h>
#include <stdint.h>

using namespace nvcuda;

// ---------------- problem constants ----------------
#define N1 3000
#define N2 2500
#define N3 2500
#define NTOT 8000
#define NPAD 8192
#define IN_F 128
#define OUT_F 64
#define HEADS 2
#define MSTR 256               // mask words per row (250 used, rest zero pad)

#define MROWS 128              // rows per k_att CTA
#define TJ 128                 // K per j-tile
#define NTILE_J 63             // ceil(8000/128); tail js zero via padded ffh/mask/WhT
#define IBLK 63                // ceil(8000/128) row blocks

#define PSTR 136               // bf16 tile row stride (272B: conflict-free)
#define CSTR 68                // f32 C tile row stride

// ---------------- device scratch ----------------
__device__ __nv_bfloat16 g_WhT[HEADS * OUT_F * NPAD];  // [head*64+o][n] bf16, 2MB
__device__ float    g_E1[HEADS * NPAD];
__device__ float    g_E2[HEADS * NPAD];
__device__ unsigned g_ffh[HEADS * NPAD];               // bf16x2 {F1,F2} per node
__device__ unsigned g_mask[NPAD * MSTR];               // 8.4MB bitmask (zero pad)
__device__ float    g_x2[NTOT * HEADS * OUT_F];        // 4MB

// ---------------- helpers ----------------
static __device__ __forceinline__ unsigned long long dup2(float x) {
    unsigned long long r;
    asm("mov.b64 %0, {%1, %2};" : "=l"(r) : "f"(x), "f"(x));
    return r;
}
static __device__ __forceinline__ void fma2(unsigned long long &acc,
                                            unsigned long long a, unsigned long long b) {
    asm("fma.rn.f32x2 %0, %1, %2, %0;" : "+l"(acc) : "l"(a), "l"(b));
}
static __device__ __forceinline__ float2 upk(unsigned long long v) {
    float2 f;
    asm("mov.b64 {%0, %1}, %2;" : "=f"(f.x), "=f"(f.y) : "l"(v));
    return f;
}
static __device__ __forceinline__ unsigned cvt_bf16x2(float lo, float hi) {
    unsigned r;
    asm("cvt.rn.satfinite.bf16x2.f32 %0, %1, %2;" : "=r"(r) : "f"(hi), "f"(lo));
    return r;
}
static __device__ __forceinline__ unsigned mul_bf16x2(unsigned a, unsigned b) {
    unsigned r;
    asm("mul.bf16x2 %0, %1, %2;" : "=r"(r) : "r"(a), "r"(b));
    return r;
}
static __device__ __forceinline__ unsigned max_bf16x2(unsigned a, unsigned b) {
    unsigned r;
    asm("max.bf16x2 %0, %1, %2;" : "=r"(r) : "r"(a), "r"(b));
    return r;
}
static __device__ __forceinline__ void cp16(void* dst_smem, const void* src) {
    unsigned d = (unsigned)__cvta_generic_to_shared(dst_smem);
    asm volatile("cp.async.ca.shared.global [%0], [%1], 16;" :: "r"(d), "l"(src) : "memory");
}
#define CP_COMMIT() asm volatile("cp.async.commit_group;" ::: "memory")
#define CP_WAIT0()  asm volatile("cp.async.wait_group 0;" ::: "memory")

// ---------------- kernel 1: per-node scalars (k_prep fused in) ----------------
__global__ void __launch_bounds__(256) k_scal(const float* __restrict__ h,
                                              const float* __restrict__ Ws,
                                              const float* __restrict__ ap) {
    __shared__ float su[2][2][IN_F];           // [head][which][f]
    const int t = threadIdx.x;

#pragma unroll
    for (int d = 0; d < 2; ++d) {
        const int id = t + 256 * d;            // 0..511
        const int hd = id >> 8, which = (id >> 7) & 1, f = id & 127;
        const float4* w = (const float4*)(Ws + hd * (IN_F * OUT_F) + f * OUT_F);
        const float4* a = (const float4*)(ap + hd * 2 * OUT_F + which * OUT_F);
        float acc = 0.f;
#pragma unroll
        for (int k = 0; k < OUT_F / 4; ++k) {
            float4 wv = w[k], av = a[k];
            acc += wv.x * av.x + wv.y * av.y + wv.z * av.z + wv.w * av.w;
        }
        su[hd][which][f] = acc;
    }
    __syncthreads();

    const int idx = blockIdx.x * 256 + t;
    if (idx >= HEADS * NTOT) return;
    const int hd = idx / NTOT, i = idx % NTOT;
    const int g = hd * NPAD + i;
    const float4* hr = (const float4*)(h + i * IN_F);
    const float4* u1 = (const float4*)(&su[hd][0][0]);
    const float4* u2 = (const float4*)(&su[hd][1][0]);
    float c = 0.f, s = 0.f;
#pragma unroll
    for (int k = 0; k < IN_F / 4; ++k) {
        float4 hv = hr[k], x = u1[k], y = u2[k];
        c += hv.x * x.x + hv.y * x.y + hv.z * x.z + hv.w * x.w;
        s += hv.x * y.x + hv.y * y.y + hv.z * y.z + hv.w * y.w;
    }
    g_E1[g]  = __expf(c);
    g_E2[g]  = __expf(0.2f * c);
    g_ffh[g] = cvt_bf16x2(__expf(s), __expf(0.2f * s));   // {lo=F1, hi=F2}
}

// ---------------- kernel 2: WhT (bf16, transposed) = (h @ Ws)^T ----------------
__global__ void __launch_bounds__(256) k_wh(const float* __restrict__ h,
                                            const float* __restrict__ Ws) {
    extern __shared__ float wsm[];
    float* sh = wsm;                 // [k][n pad 68]
    float* sW = wsm + 128 * 68;      // [k][ho=head*64+o]
    const int tid = threadIdx.x;
    const int n0 = blockIdx.x * 64;

#pragma unroll
    for (int e = 0; e < 16; ++e) {
        const int idx = tid + 256 * e;
        const int hd = idx >> 11, rem = idx & 2047, k = rem >> 4, o4 = rem & 15;
        float4 v = ((const float4*)Ws)[idx];
        *(float4*)&sW[k * 128 + hd * 64 + o4 * 4] = v;
    }
#pragma unroll
    for (int e = 0; e < 8; ++e) {
        const int idx = tid + 256 * e;
        const int n = idx >> 5, k4 = idx & 31;
        float4 v = *(const float4*)(h + (n0 + n) * IN_F + k4 * 4);
        sh[(k4 * 4 + 0) * 68 + n] = v.x;
        sh[(k4 * 4 + 1) * 68 + n] = v.y;
        sh[(k4 * 4 + 2) * 68 + n] = v.z;
        sh[(k4 * 4 + 3) * 68 + n] = v.w;
    }
    __syncthreads();

    const int tx = tid & 15, ty = tid >> 4;     // 8 ho x 4 n per thread
    unsigned long long acc[4][4];
#pragma unroll
    for (int r = 0; r < 4; ++r)
#pragma unroll
        for (int c = 0; c < 4; ++c) acc[r][c] = 0ull;

#pragma unroll 4
    for (int k = 0; k < IN_F; ++k) {
        const float4 hv = *(const float4*)&sh[k * 68 + ty * 4];
        const ulonglong2 wA = *(const ulonglong2*)&sW[k * 128 + tx * 8];
        const ulonglong2 wB = *(const ulonglong2*)&sW[k * 128 + tx * 8 + 4];
        const float hr[4] = {hv.x, hv.y, hv.z, hv.w};
#pragma unroll
        for (int r = 0; r < 4; ++r) {
            const unsigned long long hd2 = dup2(hr[r]);
            fma2(acc[r][0], hd2, wA.x); fma2(acc[r][1], hd2, wA.y);
            fma2(acc[r][2], hd2, wB.x); fma2(acc[r][3], hd2, wB.y);
        }
    }

    float v[4][8];
#pragma unroll
    for (int r = 0; r < 4; ++r)
#pragma unroll
        for (int c = 0; c < 4; ++c) {
            float2 f = upk(acc[r][c]);
            v[r][2 * c] = f.x; v[r][2 * c + 1] = f.y;
        }
#pragma unroll
    for (int hh = 0; hh < 8; ++hh) {
        const int ho = tx * 8 + hh;
        unsigned u0 = cvt_bf16x2(v[0][hh], v[1][hh]);
        unsigned u1 = cvt_bf16x2(v[2][hh], v[3][hh]);
        *(uint2*)((char*)g_WhT + (ho * NPAD + n0 + ty * 4) * 2) = make_uint2(u0, u1);
    }
}

// ---------------- kernel 3: pack block-mask into bitmask (R8 proven, MSTR rows) ----
static __device__ __forceinline__ int4 mask4(
    int i, int j4,
    const int* __restrict__ A1,  const int* __restrict__ A2,  const int* __restrict__ A3,
    const int* __restrict__ A12, const int* __restrict__ A13, const int* __restrict__ A23,
    const int* __restrict__ A21, const int* __restrict__ A31, const int* __restrict__ A32) {
    const int j = j4 * 4;
    if (i < N1) {
        if (j < N1) return *(const int4*)(A1 + i * N1 + j);
        if (j < N1 + N2) return *(const int4*)(A12 + i * N2 + (j - N1));
        return *(const int4*)(A13 + i * N3 + (j - N1 - N2));
    } else if (i < N1 + N2) {
        const int ii = i - N1;
        if (j < N1) return *(const int4*)(A21 + ii * N1 + j);
        if (j < N1 + N2) return *(const int4*)(A2 + ii * N2 + (j - N1));
        return *(const int4*)(A23 + ii * N3 + (j - N1 - N2));
    } else {
        const int ii = i - N1 - N2;
        if (j < N1) return *(const int4*)(A31 + ii * N1 + j);
        if (j < N1 + N2) return *(const int4*)(A32 + ii * N2 + (j - N1));
        return *(const int4*)(A3 + ii * N3 + (j - N1 - N2));
    }
}

__global__ void __launch_bounds__(256) k_maskpack(
    const int* __restrict__ A1,  const int* __restrict__ A2,  const int* __restrict__ A3,
    const int* __restrict__ A12, const int* __restrict__ A13, const int* __restrict__ A23,
    const int* __restrict__ A21, const int* __restrict__ A31, const int* __restrict__ A32) {
    const int row  = blockIdx.x;
    const int t    = threadIdx.x;
    const int lane = t & 31;
    const unsigned gmask = 0xFFu << ((lane >> 3) << 3);
    const int shift = (lane & 7) * 4;

    int4 v[8];
#pragma unroll
    for (int it = 0; it < 8; ++it) {
        const int idx4 = it * 256 + t;           // int4 index within row (0..1999)
        if (idx4 < 2000)
            v[it] = mask4(row, idx4, A1, A2, A3, A12, A13, A23, A21, A31, A32);
    }
#pragma unroll
    for (int it = 0; it < 8; ++it) {
        const int idx4 = it * 256 + t;
        if (idx4 < 2000) {
            const int4 a = v[it];
            unsigned nib = (unsigned)(a.x > 0) | ((unsigned)(a.y > 0) << 1)
                         | ((unsigned)(a.z > 0) << 2) | ((unsigned)(a.w > 0) << 3);
            const unsigned word = __reduce_or_sync(gmask, nib << shift);
            if ((lane & 7) == 0)
                g_mask[row * MSTR + (idx4 >> 3)] = word;
        }
    }
}

// ---------------- kernel 4: fused attention, 32x32 warp tiles + k-split ----------------
// grid (63, 2), 512 threads = 16 warps: kg = wid>>3, (wy,wx) = 4x2 of 32x32 tiles.
// Denominator via ones-column MMA: wx==0 warps accumulate dL/dH against a
// constant all-ones B frag -> C_den[i][*] = sum_j p_ij, exact fp32 accumulation
// of the SAME bf16 P the numerator uses. dsum chain + sDen reduction deleted.
// B tile staged by cp.async (issued post-sync into the idle buffer; wait_group 0
// one full compute phase later). Single __syncthreads per tile.
#define PB_BYTES (MROWS * PSTR * 2)    // 34816
#define BB_BYTES (OUT_F * PSTR * 2)    // 17408
#define FF_BYTES (TJ * 4)              // 512
#define ATT_SMEM (2 * PB_BYTES + 2 * BB_BYTES + 2 * FF_BYTES)   // 105472

__global__ void __launch_bounds__(512, 1) k_att() {
    extern __shared__ char dsm[];
    __nv_bfloat16* sP[2] = {(__nv_bfloat16*)dsm,
                            (__nv_bfloat16*)(dsm + PB_BYTES)};
    __nv_bfloat16* sB[2] = {(__nv_bfloat16*)(dsm + 2 * PB_BYTES),
                            (__nv_bfloat16*)(dsm + 2 * PB_BYTES + BB_BYTES)};
    unsigned* sFF[2] = {(unsigned*)(dsm + 2 * PB_BYTES + 2 * BB_BYTES),
                        (unsigned*)(dsm + 2 * PB_BYTES + 2 * BB_BYTES + FF_BYTES)};
    float* sCa = (float*)dsm;                          // alias, post-loop
    float* sCb = sCa + MROWS * CSTR;
    float* sD  = sCb + MROWS * CSTR;                   // [2][128][16] f32 den
    __shared__ __nv_bfloat16 sOne[256];

    const int head = blockIdx.y;
    const int i0   = blockIdx.x * MROWS;
    const int hb   = head * NPAD;
    const int tid  = threadIdx.x;
    const int wid  = tid >> 5;

    // p-gen role: row r (0..127), j-quarter q (0..3) -> 32 js
    const int r = tid & 127;
    const int q = tid >> 7;
    const unsigned epk = cvt_bf16x2(g_E1[hb + i0 + r], g_E2[hb + i0 + r]); // {e1,e2}
    const unsigned* mrow = g_mask + (i0 + r) * MSTR;
    const int jl0 = q * 32;
    const unsigned* ffh = g_ffh + hb;

    // B-stage role: two 16B granules via cp.async
    const int g0 = tid * 2;
    const int bo = g0 >> 4, bg = g0 & 15;
    const char* bsrc = (const char*)g_WhT + ((head * OUT_F + bo) * NPAD) * 2 + bg * 16;
    const int bdst = bo * PSTR + bg * 8;

    // wmma role: kg-split, 4x2 grid of 32x32 tiles
    const int kg = wid >> 3;
    const int wy = wid & 3, wx = (wid >> 2) & 1;
    wmma::fragment<wmma::accumulator, 16, 16, 16, float> c00, c01, c10, c11, dL, dH;
    wmma::fill_fragment(c00, 0.f);
    wmma::fill_fragment(c01, 0.f);
    wmma::fill_fragment(c10, 0.f);
    wmma::fill_fragment(c11, 0.f);
    wmma::fill_fragment(dL, 0.f);
    wmma::fill_fragment(dH, 0.f);
    wmma::fragment<wmma::matrix_b, 16, 16, 16, __nv_bfloat16, wmma::col_major> bOne;

    if (tid < 256) sOne[tid] = __float2bfloat16(1.0f);

    // prologue: B(0) via cp.async; sFF[0] staged; mask/ffh prefetch
    cp16(sB[0] + bdst, bsrc);
    cp16(sB[0] + bdst + 8, bsrc + 16);
    CP_COMMIT();
    unsigned nmw = mrow[q];
    uint4 nffu;
    if (tid < 32) {
        *(uint4*)(sFF[0] + tid * 4) = *(const uint4*)(ffh + tid * 4);
        nffu = *(const uint4*)(ffh + TJ + tid * 4);
    }
    __syncthreads();                   // sOne + sFF[0] visible
    wmma::load_matrix_sync(bOne, sOne, 16);

#pragma unroll 1
    for (int jt = 0; jt < NTILE_J; ++jt) {
        const int b = jt & 1;

        // ---- STS phase: P tile jt into buf[b] (packed bf16x2 p-gen) ----
        {
            const unsigned mw = nmw;
            const unsigned* ffb = sFF[b] + jl0;
            uint4* dvec = (uint4*)(sP[b] + r * PSTR + jl0);
#pragma unroll
            for (int gq = 0; gq < 4; ++gq) {
                unsigned pk[4];
#pragma unroll
                for (int e = 0; e < 4; ++e) {
                    const int k2 = gq * 4 + e;
                    const uint2 ww = *(const uint2*)(ffb + 2 * k2);
                    const unsigned w0 = (mw & (1u << (2 * k2))) ? ww.x : 0u;
                    const unsigned w1 = (mw & (2u << (2 * k2))) ? ww.y : 0u;
                    const unsigned m0 = mul_bf16x2(w0, epk);
                    const unsigned m1 = mul_bf16x2(w1, epk);
                    const unsigned lo = __byte_perm(m0, m1, 0x5410);
                    const unsigned hi = __byte_perm(m0, m1, 0x7632);
                    pk[e] = max_bf16x2(lo, hi);
                }
                dvec[gq] = make_uint4(pk[0], pk[1], pk[2], pk[3]);
            }
        }
        if (jt + 1 < NTILE_J && tid < 32)
            *(uint4*)(sFF[b ^ 1] + tid * 4) = nffu;   // ffh for tile jt+1

        // ---- prefetch mask(jt+1) / ffh(jt+2) ----
        if (jt + 1 < NTILE_J) {
            nmw = mrow[(jt + 1) * 4 + q];
            if (jt + 2 < NTILE_J && tid < 32)
                nffu = *(const uint4*)(ffh + (jt + 2) * TJ + tid * 4);
        }

        CP_WAIT0();                    // B(jt) in buf[b] complete
        __syncthreads();               // tiles ready; prior compute drained

        // ---- issue B(jt+1) into buf[b^1] (all threads past compute(jt-1)) ----
        if (jt + 1 < NTILE_J) {
            const int jb = (jt + 1) * TJ;
            cp16(sB[b ^ 1] + bdst, bsrc + jb * 2);
            cp16(sB[b ^ 1] + bdst + 8, bsrc + jb * 2 + 16);
        }
        CP_COMMIT();

        // ---- compute(jt) from buf[b]: this warp's 4 k-steps ----
#pragma unroll
        for (int ks = 0; ks < 4; ++ks) {
            const int k = kg * 4 + ks;
            wmma::fragment<wmma::matrix_a, 16, 16, 16, __nv_bfloat16, wmma::row_major> aL, aH;
            wmma::fragment<wmma::matrix_b, 16, 16, 16, __nv_bfloat16, wmma::col_major> b0, b1;
            wmma::load_matrix_sync(aL, sP[b] + (wy * 32) * PSTR + k * 16, PSTR);
            wmma::load_matrix_sync(aH, sP[b] + (wy * 32 + 16) * PSTR + k * 16, PSTR);
            wmma::load_matrix_sync(b0, sB[b] + (wx * 32) * PSTR + k * 16, PSTR);
            wmma::load_matrix_sync(b1, sB[b] + (wx * 32 + 16) * PSTR + k * 16, PSTR);
            wmma::mma_sync(c00, aL, b0, c00);
            wmma::mma_sync(c01, aL, b1, c01);
            wmma::mma_sync(c10, aH, b0, c10);
            wmma::mma_sync(c11, aH, b1, c11);
            if (wx == 0) {             // denominator: row-sums via ones column
                wmma::mma_sync(dL, aL, bOne, dL);
                wmma::mma_sync(dH, aH, bOne, dH);
            }
        }
    }

    CP_WAIT0();                        // drain trailing (empty) async group
    __syncthreads();                   // mainloop fully done; safe to alias

    // store partial C per k-group + den tiles
    {
        float* dst = (kg == 0) ? sCa : sCb;
        const int rb = wy * 32, cb = wx * 32;
        wmma::store_matrix_sync(dst + rb * CSTR + cb,               c00, CSTR, wmma::mem_row_major);
        wmma::store_matrix_sync(dst + rb * CSTR + cb + 16,          c01, CSTR, wmma::mem_row_major);
        wmma::store_matrix_sync(dst + (rb + 16) * CSTR + cb,        c10, CSTR, wmma::mem_row_major);
        wmma::store_matrix_sync(dst + (rb + 16) * CSTR + cb + 16,   c11, CSTR, wmma::mem_row_major);
        if (wx == 0) {
            wmma::store_matrix_sync(sD + kg * (MROWS * 16) + (wy * 32) * 16,
                                    dL, 16, wmma::mem_row_major);
            wmma::store_matrix_sync(sD + kg * (MROWS * 16) + (wy * 32 + 16) * 16,
                                    dH, 16, wmma::mem_row_major);
        }
    }
    __syncthreads();

    // epilogue: merge k-groups, normalize, ELU, write
    const int row = tid >> 2, cg = tid & 3;
    if (i0 + row < NTOT) {
        const float den = sD[row * 16] + sD[MROWS * 16 + row * 16];
        const float inv = 1.f / den;
        const float* sa = sCa + row * CSTR + cg * 16;
        const float* sb = sCb + row * CSTR + cg * 16;
        float* op = g_x2 + (i0 + row) * (HEADS * OUT_F) + head * OUT_F + cg * 16;
#pragma unroll
        for (int c4 = 0; c4 < 4; ++c4) {
            float4 va = *(const float4*)(sa + c4 * 4);
            float4 vb = *(const float4*)(sb + c4 * 4);
            float x0 = (va.x + vb.x) * inv, x1 = (va.y + vb.y) * inv;
            float x2 = (va.z + vb.z) * inv, x3 = (va.w + vb.w) * inv;
            x0 = (x0 > 0.f) ? x0 : expm1f(x0);
            x1 = (x1 > 0.f) ? x1 : expm1f(x1);
            x2 = (x2 > 0.f) ? x2 : expm1f(x2);
            x3 = (x3 > 0.f) ? x3 : expm1f(x3);
            *(float4*)(op + c4 * 4) = make_float4(x0, x1, x2, x3);
        }
    }
}

// ---------------- kernel 5: log_softmax (128-wide) + permuted row write ----------------
__global__ void __launch_bounds__(256) k_lsm(float* __restrict__ out) {
    const int lane = threadIdx.x & 31;
    const int i = blockIdx.x * 8 + (threadIdx.x >> 5);
    float4 v = ((const float4*)(g_x2 + i * 128))[lane];
    float mx = fmaxf(fmaxf(v.x, v.y), fmaxf(v.z, v.w));
#pragma unroll
    for (int off = 16; off > 0; off >>= 1)
        mx = fmaxf(mx, __shfl_xor_sync(0xffffffffu, mx, off));
    float sum = __expf(v.x - mx) + __expf(v.y - mx) + __expf(v.z - mx) + __expf(v.w - mx);
#pragma unroll
    for (int off = 16; off > 0; off >>= 1)
        sum += __shfl_xor_sync(0xffffffffu, sum, off);
    const float lse = mx + logf(sum);
    const int orow = (i < N1 + N2) ? (i + N3) : (i - (N1 + N2));
    float4 o = make_float4(v.x - lse, v.y - lse, v.z - lse, v.w - lse);
    ((float4*)out)[orow * 32 + lane] = o;
}

// ---------------- launch ----------------
// Order keeps k_att at ncu launch index 3 (-s 5 -c 1 profiles index 3).
extern "C" void kernel_launch(void* const* d_in, const int* in_sizes, int n_in,
                              void* d_out, int out_size) {
    const float* h   = (const float*)d_in[0];
    const int*   A1  = (const int*)d_in[1];
    const int*   A2  = (const int*)d_in[2];
    const int*   A3  = (const int*)d_in[3];
    const int*   A12 = (const int*)d_in[4];
    const int*   A13 = (const int*)d_in[5];
    const int*   A23 = (const int*)d_in[6];
    const int*   A21 = (const int*)d_in[7];
    const int*   A31 = (const int*)d_in[8];
    const int*   A32 = (const int*)d_in[9];
    const float* Ws  = (const float*)d_in[10];
    const float* ap  = (const float*)d_in[11];

    const int wh_smem = (128 * 68 + 128 * 128) * sizeof(float);   // 100352
    cudaFuncSetAttribute(k_wh,  cudaFuncAttributeMaxDynamicSharedMemorySize, wh_smem);
    cudaFuncSetAttribute(k_att, cudaFuncAttributeMaxDynamicSharedMemorySize, ATT_SMEM);

    k_maskpack<<<NTOT, 256>>>(A1, A2, A3, A12, A13, A23, A21, A31, A32);
    k_scal<<<(HEADS * NTOT + 255) / 256, 256>>>(h, Ws, ap);
    k_wh<<<NTOT / 64, 256, wh_smem>>>(h, Ws);
    k_att<<<dim3(IBLK, HEADS), 512, ATT_SMEM>>>();
    k_lsm<<<NTOT / 8, 256>>>((float*)d_out);
}